// round 2
// baseline (speedup 1.0000x reference)
#include <cuda_runtime.h>

#define N_NODES 100000
#define N_EDGES 1600000
#define F_IN 48
#define F_HID 16
#define F_OUT 16

// Scratch (device globals — no allocation allowed)
__device__ float g_y0[N_NODES * 16];   // x @ W1[0]
__device__ float g_y1[N_NODES * 16];   // x @ W1[1]
__device__ float g_r1[N_NODES * 16];   // x @ root1 + b1
__device__ float g_agg[N_NODES * 16];  // shared accumulator for both passes
__device__ float g_z0[N_NODES * 16];   // h @ W2[0]
__device__ float g_z1[N_NODES * 16];   // h @ W2[1]
__device__ float g_r2[N_NODES * 16];   // h @ root2 + b2
__device__ int   g_cnt[N_NODES];       // in-degree (same for both layers)
__device__ int   g_is64;               // 1 if edge_index is int64, 0 if int32

// ---------------------------------------------------------------------------
// Kernel 0: detect edge_index dtype. For int64 (values < 2^31) every odd
// 32-bit word is the zero high-half; for int32 they are random node ids.
// Scans the first 4096 words (16 KB — safe under either dtype).
// ---------------------------------------------------------------------------
__global__ void detect_dtype(const unsigned int* __restrict__ ei_words)
{
    __shared__ int any_nz;
    if (threadIdx.x == 0) any_nz = 0;
    __syncthreads();
    unsigned int v = 0;
    for (int i = threadIdx.x; i < 2048; i += 256)
        v |= ei_words[2 * i + 1];          // odd words
    if (v) atomicOr(&any_nz, 1);
    __syncthreads();
    if (threadIdx.x == 0) g_is64 = any_nz ? 0 : 1;
}

// ---------------------------------------------------------------------------
// Kernel 1: per-node precompute for layer 1 (+ zero agg/cnt for replay safety)
// Block = 256 threads = 16 nodes x 16 output features.
// ---------------------------------------------------------------------------
__global__ __launch_bounds__(256) void precompute1(
    const float* __restrict__ x,
    const float* __restrict__ W1,     // [2,48,16]
    const float* __restrict__ root1,  // [48,16]
    const float* __restrict__ b1)     // [16]
{
    __shared__ float sW0[F_IN * 16];
    __shared__ float sW1[F_IN * 16];
    __shared__ float sR [F_IN * 16];
    __shared__ float sx [16 * F_IN];

    int tid = threadIdx.x;
    for (int i = tid; i < F_IN * 16; i += 256) {
        sW0[i] = W1[i];
        sW1[i] = W1[F_IN * 16 + i];
        sR[i]  = root1[i];
    }
    int base = blockIdx.x * 16;  // first node of this block
    for (int i = tid; i < 16 * F_IN; i += 256) {
        sx[i] = x[base * F_IN + i];
    }
    __syncthreads();

    int nl = tid >> 4;
    int f  = tid & 15;
    int node = base + nl;

    float a0 = 0.f, a1 = 0.f, ar = b1[f];
    #pragma unroll
    for (int c = 0; c < F_IN; c++) {
        float xv = sx[nl * F_IN + c];
        a0 = fmaf(xv, sW0[c * 16 + f], a0);
        a1 = fmaf(xv, sW1[c * 16 + f], a1);
        ar = fmaf(xv, sR [c * 16 + f], ar);
    }
    int o = node * 16 + f;
    g_y0[o] = a0;
    g_y1[o] = a1;
    g_r1[o] = ar;
    g_agg[o] = 0.f;          // zero accumulator for pass 1 (replay-safe)
    if (f == 0) g_cnt[node] = 0;
}

// ---------------------------------------------------------------------------
// Kernel 2/4: edge scatter. Thread = (edge, feature). LAYER=0 uses y0/y1 and
// also accumulates the degree count; LAYER=1 uses z0/z1.
// ---------------------------------------------------------------------------
template <int LAYER>
__global__ __launch_bounds__(256) void edge_pass(
    const void* __restrict__ ei_raw,    // [2, N_EDGES] int32 or int64
    const float* __restrict__ ea)       // [N_EDGES] (u)
{
    int idx = blockIdx.x * 256 + threadIdx.x;   // < N_EDGES*16 = 25.6M
    int e = idx >> 4;
    int f = idx & 15;

    int src, dst;
    if (g_is64) {
        const long long* ei = (const long long*)ei_raw;
        src = (int)ei[e];
        dst = (int)ei[N_EDGES + e];
    } else {
        const int* ei = (const int*)ei_raw;
        src = ei[e];
        dst = ei[N_EDGES + e];
    }
    // Defensive: wrong-dtype garbage becomes a measurable error, not a trap.
    if ((unsigned)src >= N_NODES || (unsigned)dst >= N_NODES) return;

    float u = __ldg(&ea[e]);

    const float* __restrict__ s0 = LAYER ? g_z0 : g_y0;
    const float* __restrict__ s1 = LAYER ? g_z1 : g_y1;

    float a = s0[src * 16 + f];
    float b = s1[src * 16 + f];
    float msg = fmaf(u, b - a, a);      // (1-u)*a + u*b

    atomicAdd(&g_agg[dst * 16 + f], msg);
    if (LAYER == 0 && f == 0) atomicAdd(&g_cnt[dst], 1);
}

// ---------------------------------------------------------------------------
// Kernel 3: finalize layer 1 (mean + root + bias + ELU) fused with the
// layer-2 per-node precompute. h never hits global memory.
// Also re-zeros agg in place for pass 2.
// ---------------------------------------------------------------------------
__global__ __launch_bounds__(256) void mid_fused(
    const float* __restrict__ W2,     // [2,16,16]
    const float* __restrict__ root2,  // [16,16]
    const float* __restrict__ b2)     // [16]
{
    __shared__ float sW0[16 * 16];
    __shared__ float sW1[16 * 16];
    __shared__ float sR [16 * 16];
    __shared__ float sh [16 * 16];

    int tid = threadIdx.x;
    sW0[tid] = W2[tid];
    sW1[tid] = W2[256 + tid];
    sR [tid] = root2[tid];

    int base = blockIdx.x * 16;
    int nl = tid >> 4;
    int f  = tid & 15;
    int node = base + nl;
    int o = node * 16 + f;

    float cnt = (float)g_cnt[node];
    float v = g_agg[o] / fmaxf(cnt, 1.f) + g_r1[o];
    v = (v > 0.f) ? v : expm1f(v);     // ELU(alpha=1)
    sh[tid] = v;
    g_agg[o] = 0.f;                    // zero accumulator for pass 2
    __syncthreads();

    float a0 = 0.f, a1 = 0.f, ar = b2[f];
    #pragma unroll
    for (int c = 0; c < F_HID; c++) {
        float hv = sh[nl * 16 + c];
        a0 = fmaf(hv, sW0[c * 16 + f], a0);
        a1 = fmaf(hv, sW1[c * 16 + f], a1);
        ar = fmaf(hv, sR [c * 16 + f], ar);
    }
    g_z0[o] = a0;
    g_z1[o] = a1;
    g_r2[o] = ar;
}

// ---------------------------------------------------------------------------
// Kernel 5: finalize layer 2 (mean + root + bias) + log_softmax over 16 feats.
// 16-lane shfl reduction (offsets 8..1 stay inside each 16-lane half-warp).
// ---------------------------------------------------------------------------
__global__ __launch_bounds__(256) void finalize2(float* __restrict__ out)
{
    int idx = blockIdx.x * 256 + threadIdx.x;   // < N_NODES*16
    int node = idx >> 4;

    float cnt = (float)g_cnt[node];
    float v = g_agg[idx] / fmaxf(cnt, 1.f) + g_r2[idx];

    float mx = v;
    #pragma unroll
    for (int o = 8; o >= 1; o >>= 1)
        mx = fmaxf(mx, __shfl_xor_sync(0xffffffffu, mx, o));

    float ex = expf(v - mx);
    float s = ex;
    #pragma unroll
    for (int o = 8; o >= 1; o >>= 1)
        s += __shfl_xor_sync(0xffffffffu, s, o);

    out[idx] = v - mx - logf(s);
}

// ---------------------------------------------------------------------------
extern "C" void kernel_launch(void* const* d_in, const int* in_sizes, int n_in,
                              void* d_out, int out_size)
{
    const float* x     = (const float*)d_in[0];
    const float* ea    = (const float*)d_in[1];
    const void*  ei    = d_in[2];
    const float* W1    = (const float*)d_in[3];
    const float* root1 = (const float*)d_in[4];
    const float* b1    = (const float*)d_in[5];
    const float* W2    = (const float*)d_in[6];
    const float* root2 = (const float*)d_in[7];
    const float* b2    = (const float*)d_in[8];
    float* out = (float*)d_out;

    const int node_blocks = N_NODES / 16;            // 6250
    const int edge_blocks = (N_EDGES * 16) / 256;    // 100000

    detect_dtype<<<1, 256>>>((const unsigned int*)ei);
    precompute1<<<node_blocks, 256>>>(x, W1, root1, b1);
    edge_pass<0><<<edge_blocks, 256>>>(ei, ea);
    mid_fused<<<node_blocks, 256>>>(W2, root2, b2);
    edge_pass<1><<<edge_blocks, 256>>>(ei, ea);
    finalize2<<<node_blocks, 256>>>(out);
}

// round 3
// speedup vs baseline: 1.6454x; 1.6454x over previous
#include <cuda_runtime.h>

#define N_NODES 100000
#define N_EDGES 1600000
#define F_IN 48
#define F_HID 16
#define F_OUT 16

// Scratch (device globals — no allocation allowed).
// Y/Z: interleaved per-node tables, 32 floats (= 8 float4) per node:
//   [0:16)  = x @ W[0]   (a)
//   [16:32) = x @ W[1]   (b)
__device__ float4 g_Y[N_NODES * 8];
__device__ float4 g_Z[N_NODES * 8];
__device__ float4 g_AGG[N_NODES * 4];  // 16 floats per node, 16B-aligned
__device__ float  g_r1[N_NODES * 16];  // x @ root1 + b1
__device__ float  g_r2[N_NODES * 16];  // h @ root2 + b2
__device__ int    g_cnt[N_NODES];      // in-degree (same both layers)
__device__ int    g_is64;              // 1 if edge_index is int64

__device__ __forceinline__ void red_add_v4(float4* addr, float4 v)
{
    asm volatile("red.global.add.v4.f32 [%0], {%1, %2, %3, %4};"
                 :: "l"(addr), "f"(v.x), "f"(v.y), "f"(v.z), "f"(v.w)
                 : "memory");
}

// ---------------------------------------------------------------------------
// Kernel 0: detect edge_index dtype (int64 values < 2^31 -> odd words zero).
// ---------------------------------------------------------------------------
__global__ void detect_dtype(const unsigned int* __restrict__ ei_words)
{
    __shared__ int any_nz;
    if (threadIdx.x == 0) any_nz = 0;
    __syncthreads();
    unsigned int v = 0;
    for (int i = threadIdx.x; i < 2048; i += 256)
        v |= ei_words[2 * i + 1];
    if (v) atomicOr(&any_nz, 1);
    __syncthreads();
    if (threadIdx.x == 0) g_is64 = any_nz ? 0 : 1;
}

// ---------------------------------------------------------------------------
// Kernel 1: layer-1 per-node precompute (+ zero agg/cnt for replay safety).
// Block = 256 threads = 16 nodes x 16 output features.
// ---------------------------------------------------------------------------
__global__ __launch_bounds__(256) void precompute1(
    const float* __restrict__ x,
    const float* __restrict__ W1,     // [2,48,16]
    const float* __restrict__ root1,  // [48,16]
    const float* __restrict__ b1)     // [16]
{
    __shared__ float sW0[F_IN * 16];
    __shared__ float sW1[F_IN * 16];
    __shared__ float sR [F_IN * 16];
    __shared__ float sx [16 * F_IN];

    int tid = threadIdx.x;
    for (int i = tid; i < F_IN * 16; i += 256) {
        sW0[i] = W1[i];
        sW1[i] = W1[F_IN * 16 + i];
        sR[i]  = root1[i];
    }
    int base = blockIdx.x * 16;
    for (int i = tid; i < 16 * F_IN; i += 256)
        sx[i] = x[base * F_IN + i];
    __syncthreads();

    int nl = tid >> 4;
    int f  = tid & 15;
    int node = base + nl;

    float a0 = 0.f, a1 = 0.f, ar = b1[f];
    #pragma unroll
    for (int c = 0; c < F_IN; c++) {
        float xv = sx[nl * F_IN + c];
        a0 = fmaf(xv, sW0[c * 16 + f], a0);
        a1 = fmaf(xv, sW1[c * 16 + f], a1);
        ar = fmaf(xv, sR [c * 16 + f], ar);
    }
    float* Y = (float*)g_Y;
    Y[node * 32 + f]      = a0;
    Y[node * 32 + 16 + f] = a1;
    g_r1[node * 16 + f] = ar;
    ((float*)g_AGG)[node * 16 + f] = 0.f;   // zero accumulator for pass 1
    if (f == 0) g_cnt[node] = 0;
}

// ---------------------------------------------------------------------------
// Kernel 2/4: edge scatter. Thread = (edge, feature-quad). 4 features per
// thread: float4 gathers + one red.global.add.v4.f32 per thread.
// ---------------------------------------------------------------------------
template <int LAYER>
__global__ __launch_bounds__(256) void edge_pass(
    const void* __restrict__ ei_raw,    // [2, N_EDGES] int32 or int64
    const float* __restrict__ ea)       // [N_EDGES] (u)
{
    int idx = blockIdx.x * 256 + threadIdx.x;   // < N_EDGES*4 = 6.4M
    int e = idx >> 2;
    int q = idx & 3;

    int src, dst;
    if (g_is64) {
        const long long* ei = (const long long*)ei_raw;
        src = (int)__ldg(&ei[e]);
        dst = (int)__ldg(&ei[N_EDGES + e]);
    } else {
        const int* ei = (const int*)ei_raw;
        src = __ldg(&ei[e]);
        dst = __ldg(&ei[N_EDGES + e]);
    }
    if ((unsigned)src >= N_NODES || (unsigned)dst >= N_NODES) return;

    float u = __ldg(&ea[e]);

    const float4* __restrict__ Y = LAYER ? g_Z : g_Y;
    float4 a = Y[src * 8 + q];
    float4 b = Y[src * 8 + 4 + q];

    float4 m;
    m.x = fmaf(u, b.x - a.x, a.x);
    m.y = fmaf(u, b.y - a.y, a.y);
    m.z = fmaf(u, b.z - a.z, a.z);
    m.w = fmaf(u, b.w - a.w, a.w);

    red_add_v4(&g_AGG[dst * 4 + q], m);
    if (LAYER == 0 && q == 0) atomicAdd(&g_cnt[dst], 1);
}

// ---------------------------------------------------------------------------
// Kernel 3: finalize layer 1 (mean + root + bias + ELU) fused with the
// layer-2 per-node precompute; re-zeros agg for pass 2.
// ---------------------------------------------------------------------------
__global__ __launch_bounds__(256) void mid_fused(
    const float* __restrict__ W2,     // [2,16,16]
    const float* __restrict__ root2,  // [16,16]
    const float* __restrict__ b2)     // [16]
{
    __shared__ float sW0[16 * 16];
    __shared__ float sW1[16 * 16];
    __shared__ float sR [16 * 16];
    __shared__ float sh [16 * 16];

    int tid = threadIdx.x;
    sW0[tid] = W2[tid];
    sW1[tid] = W2[256 + tid];
    sR [tid] = root2[tid];

    int base = blockIdx.x * 16;
    int nl = tid >> 4;
    int f  = tid & 15;
    int node = base + nl;
    int o = node * 16 + f;

    float cnt = (float)g_cnt[node];
    float v = ((float*)g_AGG)[o] / fmaxf(cnt, 1.f) + g_r1[o];
    v = (v > 0.f) ? v : expm1f(v);     // ELU(alpha=1)
    sh[tid] = v;
    ((float*)g_AGG)[o] = 0.f;          // zero accumulator for pass 2
    __syncthreads();

    float a0 = 0.f, a1 = 0.f, ar = b2[f];
    #pragma unroll
    for (int c = 0; c < F_HID; c++) {
        float hv = sh[nl * 16 + c];
        a0 = fmaf(hv, sW0[c * 16 + f], a0);
        a1 = fmaf(hv, sW1[c * 16 + f], a1);
        ar = fmaf(hv, sR [c * 16 + f], ar);
    }
    float* Z = (float*)g_Z;
    Z[node * 32 + f]      = a0;
    Z[node * 32 + 16 + f] = a1;
    g_r2[o] = ar;
}

// ---------------------------------------------------------------------------
// Kernel 5: finalize layer 2 (mean + root + bias) + log_softmax over 16.
// ---------------------------------------------------------------------------
__global__ __launch_bounds__(256) void finalize2(float* __restrict__ out)
{
    int idx = blockIdx.x * 256 + threadIdx.x;   // < N_NODES*16
    int node = idx >> 4;

    float cnt = (float)g_cnt[node];
    float v = ((float*)g_AGG)[idx] / fmaxf(cnt, 1.f) + g_r2[idx];

    float mx = v;
    #pragma unroll
    for (int o = 8; o >= 1; o >>= 1)
        mx = fmaxf(mx, __shfl_xor_sync(0xffffffffu, mx, o));

    float ex = expf(v - mx);
    float s = ex;
    #pragma unroll
    for (int o = 8; o >= 1; o >>= 1)
        s += __shfl_xor_sync(0xffffffffu, s, o);

    out[idx] = v - mx - logf(s);
}

// ---------------------------------------------------------------------------
extern "C" void kernel_launch(void* const* d_in, const int* in_sizes, int n_in,
                              void* d_out, int out_size)
{
    const float* x     = (const float*)d_in[0];
    const float* ea    = (const float*)d_in[1];
    const void*  ei    = d_in[2];
    const float* W1    = (const float*)d_in[3];
    const float* root1 = (const float*)d_in[4];
    const float* b1    = (const float*)d_in[5];
    const float* W2    = (const float*)d_in[6];
    const float* root2 = (const float*)d_in[7];
    const float* b2    = (const float*)d_in[8];
    float* out = (float*)d_out;

    const int node_blocks = N_NODES / 16;            // 6250
    const int edge_blocks = (N_EDGES * 4) / 256;     // 25000

    detect_dtype<<<1, 256>>>((const unsigned int*)ei);
    precompute1<<<node_blocks, 256>>>(x, W1, root1, b1);
    edge_pass<0><<<edge_blocks, 256>>>(ei, ea);
    mid_fused<<<node_blocks, 256>>>(W2, root2, b2);
    edge_pass<1><<<edge_blocks, 256>>>(ei, ea);
    finalize2<<<node_blocks, 256>>>(out);
}